// round 12
// baseline (speedup 1.0000x reference)
#include <cuda_runtime.h>
#include <cuda_bf16.h>

#define BATCH 64
#define SRCLEN 2048
#define DIM 1024

// ---------------- device scratch (no allocations allowed) ----------------
__device__ __nv_bfloat16 g_mem_bf16[(size_t)BATCH * SRCLEN * DIM];   // 256 MB
__device__ __nv_bfloat16 g_wc_bf16[DIM * DIM];                       // 2 MB
__device__ float         g_off[BATCH * DIM];                         // 256 KB
__device__ float         g_partial[8 * BATCH * SRCLEN];              // 4 MB

// ---------------- helpers (base ISA only: no 'a'-gated features) ----------------
__device__ __forceinline__ unsigned smem_u32(const void* p) {
    unsigned a;
    asm("{ .reg .u64 t; cvta.to.shared.u64 t, %1; cvt.u32.u64 %0, t; }" : "=r"(a) : "l"(p));
    return a;
}
__device__ __forceinline__ float tanh_fast(float x) {
    float y; asm("tanh.approx.f32 %0, %1;" : "=f"(y) : "f"(x)); return y;
}

#define SWZ128(o) ((o) ^ (((o) >> 3) & 0x70))

#define CP_ASYNC16(dst, src) \
    asm volatile("cp.async.cg.shared.global [%0], [%1], 16;" :: "r"(dst), "l"(src) : "memory")
#define CP_COMMIT() asm volatile("cp.async.commit_group;" ::: "memory")
#define CP_WAIT1()  asm volatile("cp.async.wait_group 1;" ::: "memory")

__device__ __forceinline__ void ldsm_x4(unsigned& r0, unsigned& r1, unsigned& r2, unsigned& r3,
                                        unsigned addr) {
    asm volatile("ldmatrix.sync.aligned.m8n8.x4.shared.b16 {%0,%1,%2,%3}, [%4];"
                 : "=r"(r0), "=r"(r1), "=r"(r2), "=r"(r3) : "r"(addr));
}

__device__ __forceinline__ void mma_bf16(float* d, const unsigned* a, const unsigned* b) {
    asm volatile(
        "mma.sync.aligned.m16n8k16.row.col.f32.bf16.bf16.f32 "
        "{%0,%1,%2,%3}, {%4,%5,%6,%7}, {%8,%9}, {%0,%1,%2,%3};"
        : "+f"(d[0]), "+f"(d[1]), "+f"(d[2]), "+f"(d[3])
        : "r"(a[0]), "r"(a[1]), "r"(a[2]), "r"(a[3]), "r"(b[0]), "r"(b[1]));
}

// ---------------- kernel 1: fp32 -> bf16 convert ----------------
__global__ void conv_f32_bf16(const float* __restrict__ src, __nv_bfloat16* __restrict__ dst, size_t n8) {
    size_t i = (size_t)blockIdx.x * blockDim.x + threadIdx.x;
    size_t stride = (size_t)gridDim.x * blockDim.x;
    for (; i < n8; i += stride) {
        float4 a = ((const float4*)src)[2 * i];
        float4 b = ((const float4*)src)[2 * i + 1];
        __nv_bfloat162 h0 = __floats2bfloat162_rn(a.x, a.y);
        __nv_bfloat162 h1 = __floats2bfloat162_rn(a.z, a.w);
        __nv_bfloat162 h2 = __floats2bfloat162_rn(b.x, b.y);
        __nv_bfloat162 h3 = __floats2bfloat162_rn(b.z, b.w);
        uint4 o;
        o.x = *reinterpret_cast<unsigned*>(&h0);
        o.y = *reinterpret_cast<unsigned*>(&h1);
        o.z = *reinterpret_cast<unsigned*>(&h2);
        o.w = *reinterpret_cast<unsigned*>(&h3);
        ((uint4*)dst)[i] = o;
    }
}

// ---------------- kernel 2: off[b,e] = bq[e] + src.Wq^T + cond.Wcond^T ----------------
__global__ void off_kernel(const float* __restrict__ src, const float* __restrict__ cond,
                           const float* __restrict__ Wq, const float* __restrict__ bq,
                           const float* __restrict__ Wcd) {
    __shared__ float Ws[2][4][DIM];  // 32 KB
    int e0 = blockIdx.x * 4;
    int t = threadIdx.x;
    for (int i = t; i < 2 * 4 * DIM; i += 256) {
        int m = i >> 12, r = (i >> 10) & 3, d = i & 1023;
        Ws[m][r][d] = (m ? Wcd : Wq)[(size_t)(e0 + r) * DIM + d];
    }
    __syncthreads();
    int w = t >> 5, l = t & 31;
    int el = w & 3;
    for (int b = (w >> 2); b < BATCH; b += 2) {
        float a1 = 0.f, a2 = 0.f;
        for (int d = l; d < DIM; d += 32) {
            a1 = fmaf(src[(size_t)b * DIM + d], Ws[0][el][d], a1);
            a2 = fmaf(cond[(size_t)b * DIM + d], Ws[1][el][d], a2);
        }
        for (int o = 16; o > 0; o >>= 1) {
            a1 += __shfl_down_sync(0xffffffffu, a1, o);
            a2 += __shfl_down_sync(0xffffffffu, a2, o);
        }
        if (l == 0) g_off[(size_t)b * DIM + e0 + el] = bq[e0 + el] + a1 + a2;
    }
}

// ---------------- kernel 3: mma.sync GEMM + fused tanh/v-dot epilogue ----------------
// CTA = 128 s-rows x 128 e-cols for one batch. grid = (8 ntile, 16 stile, 64 batch).
// Writes partial logits to g_partial[nt][b][s].
static constexpr int SM_A0 = 0;          // 16 KB (128 rows x 128B, SW128)
static constexpr int SM_A1 = 16384;
static constexpr int SM_B0 = 32768;      // 16 KB
static constexpr int SM_B1 = 49152;
static constexpr int SM_OFF = 65536;     // 512 B
static constexpr int SM_V   = 66048;     // 512 B
static constexpr int SM_PART = 66560;    // 2 x 128 x 4B = 1 KB
static constexpr int SMEM_TOTAL = 67584;

__global__ void __launch_bounds__(256, 2) gemm_align_kernel(const float* __restrict__ v) {
    extern __shared__ char smem[];
    const unsigned sb = smem_u32(smem);
    const int tid = threadIdx.x, wid = tid >> 5, lid = tid & 31;
    const int nt = blockIdx.x;           // e tile (0..7)
    const int s0 = blockIdx.y * 128;     // s tile
    const int b  = blockIdx.z;

    const __nv_bfloat16* Abase = g_mem_bf16 + ((size_t)b * SRCLEN + s0) * DIM;
    const __nv_bfloat16* Bbase = g_wc_bf16 + (size_t)nt * 128 * DIM;

    // stage offsets
    const int SMA[2] = {SM_A0, SM_A1};
    const int SMB[2] = {SM_B0, SM_B1};

    // load off/v slices for this e-tile
    if (tid < 128) {
        ((float*)(smem + SM_OFF))[tid] = g_off[(size_t)b * DIM + nt * 128 + tid];
        ((float*)(smem + SM_V))[tid] = v[nt * 128 + tid];
    }

    // async-load one 64-wide k-chunk (A and B tiles: 128 rows x 128B each)
    auto load_stage = [&](int kc, int st) {
        #pragma unroll
        for (int j = 0; j < 4; ++j) {
            int i = tid + j * 256;
            int r = i >> 3, c = i & 7;
            const void* srcA = Abase + (size_t)r * DIM + kc * 64 + c * 8;
            CP_ASYNC16(sb + SMA[st] + SWZ128(r * 128 + c * 16), srcA);
        }
        #pragma unroll
        for (int j = 0; j < 4; ++j) {
            int i = tid + j * 256;
            int r = i >> 3, c = i & 7;
            const void* srcB = Bbase + (size_t)r * DIM + kc * 64 + c * 8;
            CP_ASYNC16(sb + SMB[st] + SWZ128(r * 128 + c * 16), srcB);
        }
    };

    load_stage(0, 0); CP_COMMIT();
    load_stage(1, 1); CP_COMMIT();

    const int wm = (wid & 3) * 32;   // warp m offset (s rows)
    const int wn = (wid >> 2) * 64;  // warp n offset (e cols)

    float acc[2][8][4];
    #pragma unroll
    for (int i = 0; i < 2; ++i)
        #pragma unroll
        for (int j = 0; j < 8; ++j)
            #pragma unroll
            for (int q = 0; q < 4; ++q) acc[i][j][q] = 0.f;

    for (int kc = 0; kc < 16; ++kc) {
        CP_WAIT1();
        __syncthreads();
        const int st = kc & 1;
        const unsigned Asm = sb + SMA[st];
        const unsigned Bsm = sb + SMB[st];
        #pragma unroll
        for (int ks = 0; ks < 4; ++ks) {
            unsigned a[2][4];
            #pragma unroll
            for (int i = 0; i < 2; ++i) {
                int row = wm + i * 16 + (lid & 15);
                int col = ks * 32 + (lid >> 4) * 16;
                ldsm_x4(a[i][0], a[i][1], a[i][2], a[i][3], Asm + SWZ128(row * 128 + col));
            }
            unsigned bf[4][4];
            #pragma unroll
            for (int jj = 0; jj < 4; ++jj) {
                int row = wn + jj * 16 + (lid & 15);
                int col = ks * 32 + (lid >> 4) * 16;
                ldsm_x4(bf[jj][0], bf[jj][1], bf[jj][2], bf[jj][3], Bsm + SWZ128(row * 128 + col));
            }
            #pragma unroll
            for (int i = 0; i < 2; ++i)
                #pragma unroll
                for (int j = 0; j < 8; ++j) {
                    unsigned bb[2] = { bf[j >> 1][j & 1], bf[j >> 1][2 + (j & 1)] };
                    mma_bf16(acc[i][j], a[i], bb);
                }
        }
        __syncthreads();
        if (kc + 2 < 16) load_stage(kc + 2, st);
        CP_COMMIT();
    }

    // epilogue: partial logit = sum_e tanh(acc + off[e]) * v[e] over this tile's 128 e's
    const float* off_s = (const float*)(smem + SM_OFF);
    const float* v_s   = (const float*)(smem + SM_V);
    float pr[2][2] = {{0.f, 0.f}, {0.f, 0.f}};   // [m16 tile][row half]
    #pragma unroll
    for (int i = 0; i < 2; ++i)
        #pragma unroll
        for (int j = 0; j < 8; ++j) {
            int el = wn + j * 8 + (lid & 3) * 2;
            float o0 = off_s[el], o1 = off_s[el + 1];
            float v0 = v_s[el],   v1 = v_s[el + 1];
            pr[i][0] = fmaf(tanh_fast(acc[i][j][0] + o0), v0, pr[i][0]);
            pr[i][0] = fmaf(tanh_fast(acc[i][j][1] + o1), v1, pr[i][0]);
            pr[i][1] = fmaf(tanh_fast(acc[i][j][2] + o0), v0, pr[i][1]);
            pr[i][1] = fmaf(tanh_fast(acc[i][j][3] + o1), v1, pr[i][1]);
        }
    #pragma unroll
    for (int o = 1; o <= 2; o <<= 1) {
        pr[0][0] += __shfl_xor_sync(0xffffffffu, pr[0][0], o);
        pr[0][1] += __shfl_xor_sync(0xffffffffu, pr[0][1], o);
        pr[1][0] += __shfl_xor_sync(0xffffffffu, pr[1][0], o);
        pr[1][1] += __shfl_xor_sync(0xffffffffu, pr[1][1], o);
    }
    float* part = (float*)(smem + SM_PART) + (wid >> 2) * 128;
    if ((lid & 3) == 0) {
        int g = lid >> 2;
        part[wm + g]          = pr[0][0];
        part[wm + g + 8]      = pr[0][1];
        part[wm + 16 + g]     = pr[1][0];
        part[wm + 16 + g + 8] = pr[1][1];
    }
    __syncthreads();
    if (tid < 128) {
        float sum = ((float*)(smem + SM_PART))[tid] + ((float*)(smem + SM_PART))[128 + tid];
        g_partial[((size_t)nt * BATCH + b) * SRCLEN + s0 + tid] = sum;
    }
}

// ---------------- kernel 4: reduce partials + softmax, writes align_vectors ----------------
__global__ void softmax_kernel(float* __restrict__ p_out) {
    __shared__ float red[256];
    const int b = blockIdx.x, t = threadIdx.x;
    float vals[8];
    float m = -1e30f;
    #pragma unroll
    for (int i = 0; i < 8; ++i) {
        size_t idx = (size_t)b * SRCLEN + t + i * 256;
        float s = 0.f;
        #pragma unroll
        for (int nt = 0; nt < 8; ++nt)
            s += g_partial[(size_t)nt * BATCH * SRCLEN + idx];
        vals[i] = s;
        m = fmaxf(m, s);
    }
    red[t] = m; __syncthreads();
    for (int o = 128; o > 0; o >>= 1) { if (t < o) red[t] = fmaxf(red[t], red[t + o]); __syncthreads(); }
    const float M = red[0]; __syncthreads();
    float s = 0.f;
    #pragma unroll
    for (int i = 0; i < 8; ++i) { vals[i] = __expf(vals[i] - M); s += vals[i]; }
    red[t] = s; __syncthreads();
    for (int o = 128; o > 0; o >>= 1) { if (t < o) red[t] += red[t + o]; __syncthreads(); }
    const float inv = 1.f / red[0];
    #pragma unroll
    for (int i = 0; i < 8; ++i)
        p_out[(size_t)b * SRCLEN + t + i * 256] = vals[i] * inv;
}

// ---------------- kernel 5: c[b,d] = sum_s p[b,s] * mem[b,s,d] (fp32) ----------------
__global__ void __launch_bounds__(256) context_kernel(const float* __restrict__ mem,
                                                      const float* __restrict__ p_all,
                                                      float* __restrict__ c_out) {
    __shared__ float p[SRCLEN];
    const int b = blockIdx.y, d0 = blockIdx.x * 256, t = threadIdx.x;
    for (int i = t; i < SRCLEN; i += 256) p[i] = p_all[(size_t)b * SRCLEN + i];
    __syncthreads();
    const float* mb = mem + (size_t)b * SRCLEN * DIM + d0 + t;
    float acc = 0.f;
    #pragma unroll 8
    for (int s = 0; s < SRCLEN; ++s)
        acc = fmaf(p[s], mb[(size_t)s * DIM], acc);
    c_out[(size_t)b * DIM + d0 + t] = acc;
}

// ---------------- launch ----------------
extern "C" void kernel_launch(void* const* d_in, const int* in_sizes, int n_in,
                              void* d_out, int out_size) {
    const float* source = (const float*)d_in[0];
    const float* mem    = (const float*)d_in[1];
    const float* cond   = (const float*)d_in[2];
    const float* Wq     = (const float*)d_in[3];
    const float* bq     = (const float*)d_in[4];
    const float* Wc     = (const float*)d_in[5];
    const float* Wcd    = (const float*)d_in[6];
    const float* v      = (const float*)d_in[7];

    float* out   = (float*)d_out;
    float* c_out = out;                    // [64, 1024]
    float* p_out = out + BATCH * DIM;      // [64, 1, 2048]

    void *pmem = nullptr, *pwc = nullptr;
    cudaGetSymbolAddress(&pmem, g_mem_bf16);
    cudaGetSymbolAddress(&pwc, g_wc_bf16);

    conv_f32_bf16<<<8192, 256>>>(mem, (__nv_bfloat16*)pmem, (size_t)BATCH * SRCLEN * DIM / 8);
    conv_f32_bf16<<<512, 256>>>(Wc, (__nv_bfloat16*)pwc, (size_t)DIM * DIM / 8);
    off_kernel<<<256, 256>>>(source, cond, Wq, bq, Wcd);

    static bool attr_set = false;
    if (!attr_set) {
        cudaFuncSetAttribute(gemm_align_kernel, cudaFuncAttributeMaxDynamicSharedMemorySize, SMEM_TOTAL);
        attr_set = true;
    }
    gemm_align_kernel<<<dim3(8, 16, 64), 256, SMEM_TOTAL>>>(v);

    softmax_kernel<<<64, 256>>>(p_out);
    context_kernel<<<dim3(4, 64), 256>>>(mem, p_out, c_out);
}

// round 13
// speedup vs baseline: 1.0062x; 1.0062x over previous
#include <cuda_runtime.h>
#include <cuda_bf16.h>

#define BATCH 64
#define SRCLEN 2048
#define DIM 1024

// ---------------- device scratch (no allocations allowed) ----------------
__device__ __nv_bfloat16 g_mem_bf16[(size_t)BATCH * SRCLEN * DIM];   // 256 MB
__device__ __nv_bfloat16 g_wc_bf16[DIM * DIM];                       // 2 MB
__device__ float         g_off[BATCH * DIM];                         // 256 KB
__device__ float         g_partial[8 * BATCH * SRCLEN];              // 4 MB

// ---------------- helpers (base ISA only: no 'a'-gated features) ----------------
__device__ __forceinline__ unsigned smem_u32(const void* p) {
    unsigned a;
    asm("{ .reg .u64 t; cvta.to.shared.u64 t, %1; cvt.u32.u64 %0, t; }" : "=r"(a) : "l"(p));
    return a;
}
__device__ __forceinline__ float tanh_fast(float x) {
    float y; asm("tanh.approx.f32 %0, %1;" : "=f"(y) : "f"(x)); return y;
}

#define SWZ128(o) ((o) ^ (((o) >> 3) & 0x70))

#define CP_ASYNC16(dst, src) \
    asm volatile("cp.async.cg.shared.global [%0], [%1], 16;" :: "r"(dst), "l"(src) : "memory")
#define CP_COMMIT() asm volatile("cp.async.commit_group;" ::: "memory")
#define CP_WAIT1()  asm volatile("cp.async.wait_group 1;" ::: "memory")

__device__ __forceinline__ void ldsm_x4(unsigned& r0, unsigned& r1, unsigned& r2, unsigned& r3,
                                        unsigned addr) {
    asm volatile("ldmatrix.sync.aligned.m8n8.x4.shared.b16 {%0,%1,%2,%3}, [%4];"
                 : "=r"(r0), "=r"(r1), "=r"(r2), "=r"(r3) : "r"(addr));
}

__device__ __forceinline__ void mma_bf16(float* d, const unsigned* a, const unsigned* b) {
    asm volatile(
        "mma.sync.aligned.m16n8k16.row.col.f32.bf16.bf16.f32 "
        "{%0,%1,%2,%3}, {%4,%5,%6,%7}, {%8,%9}, {%0,%1,%2,%3};"
        : "+f"(d[0]), "+f"(d[1]), "+f"(d[2]), "+f"(d[3])
        : "r"(a[0]), "r"(a[1]), "r"(a[2]), "r"(a[3]), "r"(b[0]), "r"(b[1]));
}

// ---------------- kernel 1: fp32 -> bf16 convert ----------------
__global__ void conv_f32_bf16(const float* __restrict__ src, __nv_bfloat16* __restrict__ dst, size_t n8) {
    size_t i = (size_t)blockIdx.x * blockDim.x + threadIdx.x;
    size_t stride = (size_t)gridDim.x * blockDim.x;
    for (; i < n8; i += stride) {
        float4 a = ((const float4*)src)[2 * i];
        float4 b = ((const float4*)src)[2 * i + 1];
        __nv_bfloat162 h0 = __floats2bfloat162_rn(a.x, a.y);
        __nv_bfloat162 h1 = __floats2bfloat162_rn(a.z, a.w);
        __nv_bfloat162 h2 = __floats2bfloat162_rn(b.x, b.y);
        __nv_bfloat162 h3 = __floats2bfloat162_rn(b.z, b.w);
        uint4 o;
        o.x = *reinterpret_cast<unsigned*>(&h0);
        o.y = *reinterpret_cast<unsigned*>(&h1);
        o.z = *reinterpret_cast<unsigned*>(&h2);
        o.w = *reinterpret_cast<unsigned*>(&h3);
        ((uint4*)dst)[i] = o;
    }
}

// ---------------- kernel 2: off[b,e] = bq[e] + src.Wq^T + cond.Wcond^T ----------------
__global__ void off_kernel(const float* __restrict__ src, const float* __restrict__ cond,
                           const float* __restrict__ Wq, const float* __restrict__ bq,
                           const float* __restrict__ Wcd) {
    __shared__ float Ws[2][4][DIM];  // 32 KB
    int e0 = blockIdx.x * 4;
    int t = threadIdx.x;
    for (int i = t; i < 2 * 4 * DIM; i += 256) {
        int m = i >> 12, r = (i >> 10) & 3, d = i & 1023;
        Ws[m][r][d] = (m ? Wcd : Wq)[(size_t)(e0 + r) * DIM + d];
    }
    __syncthreads();
    int w = t >> 5, l = t & 31;
    int el = w & 3;
    for (int b = (w >> 2); b < BATCH; b += 2) {
        float a1 = 0.f, a2 = 0.f;
        for (int d = l; d < DIM; d += 32) {
            a1 = fmaf(src[(size_t)b * DIM + d], Ws[0][el][d], a1);
            a2 = fmaf(cond[(size_t)b * DIM + d], Ws[1][el][d], a2);
        }
        for (int o = 16; o > 0; o >>= 1) {
            a1 += __shfl_down_sync(0xffffffffu, a1, o);
            a2 += __shfl_down_sync(0xffffffffu, a2, o);
        }
        if (l == 0) g_off[(size_t)b * DIM + e0 + el] = bq[e0 + el] + a1 + a2;
    }
}

// ---------------- kernel 3: mma.sync GEMM + fused tanh/v-dot epilogue ----------------
// CTA = 128 s-rows x 128 e-cols for one batch. grid = (8 ntile, 16 stile, 64 batch).
// Writes partial logits to g_partial[nt][b][s].
static constexpr int SM_A0 = 0;          // 16 KB (128 rows x 128B, SW128)
static constexpr int SM_A1 = 16384;
static constexpr int SM_B0 = 32768;      // 16 KB
static constexpr int SM_B1 = 49152;
static constexpr int SM_OFF = 65536;     // 512 B
static constexpr int SM_V   = 66048;     // 512 B
static constexpr int SM_PART = 66560;    // 2 x 128 x 4B = 1 KB
static constexpr int SMEM_TOTAL = 67584;

__global__ void __launch_bounds__(256, 2) gemm_align_kernel(const float* __restrict__ v) {
    extern __shared__ char smem[];
    const unsigned sb = smem_u32(smem);
    const int tid = threadIdx.x, wid = tid >> 5, lid = tid & 31;
    const int nt = blockIdx.x;           // e tile (0..7)
    const int s0 = blockIdx.y * 128;     // s tile
    const int b  = blockIdx.z;

    const __nv_bfloat16* Abase = g_mem_bf16 + ((size_t)b * SRCLEN + s0) * DIM;
    const __nv_bfloat16* Bbase = g_wc_bf16 + (size_t)nt * 128 * DIM;

    // stage offsets
    const int SMA[2] = {SM_A0, SM_A1};
    const int SMB[2] = {SM_B0, SM_B1};

    // load off/v slices for this e-tile
    if (tid < 128) {
        ((float*)(smem + SM_OFF))[tid] = g_off[(size_t)b * DIM + nt * 128 + tid];
        ((float*)(smem + SM_V))[tid] = v[nt * 128 + tid];
    }

    // async-load one 64-wide k-chunk (A and B tiles: 128 rows x 128B each)
    auto load_stage = [&](int kc, int st) {
        #pragma unroll
        for (int j = 0; j < 4; ++j) {
            int i = tid + j * 256;
            int r = i >> 3, c = i & 7;
            const void* srcA = Abase + (size_t)r * DIM + kc * 64 + c * 8;
            CP_ASYNC16(sb + SMA[st] + SWZ128(r * 128 + c * 16), srcA);
        }
        #pragma unroll
        for (int j = 0; j < 4; ++j) {
            int i = tid + j * 256;
            int r = i >> 3, c = i & 7;
            const void* srcB = Bbase + (size_t)r * DIM + kc * 64 + c * 8;
            CP_ASYNC16(sb + SMB[st] + SWZ128(r * 128 + c * 16), srcB);
        }
    };

    load_stage(0, 0); CP_COMMIT();
    load_stage(1, 1); CP_COMMIT();

    const int wm = (wid & 3) * 32;   // warp m offset (s rows)
    const int wn = (wid >> 2) * 64;  // warp n offset (e cols)

    float acc[2][8][4];
    #pragma unroll
    for (int i = 0; i < 2; ++i)
        #pragma unroll
        for (int j = 0; j < 8; ++j)
            #pragma unroll
            for (int q = 0; q < 4; ++q) acc[i][j][q] = 0.f;

    for (int kc = 0; kc < 16; ++kc) {
        CP_WAIT1();
        __syncthreads();
        const int st = kc & 1;
        const unsigned Asm = sb + SMA[st];
        const unsigned Bsm = sb + SMB[st];
        #pragma unroll
        for (int ks = 0; ks < 4; ++ks) {
            unsigned a[2][4];
            #pragma unroll
            for (int i = 0; i < 2; ++i) {
                int row = wm + i * 16 + (lid & 15);
                int col = ks * 32 + (lid >> 4) * 16;
                ldsm_x4(a[i][0], a[i][1], a[i][2], a[i][3], Asm + SWZ128(row * 128 + col));
            }
            unsigned bf[4][4];
            #pragma unroll
            for (int jj = 0; jj < 4; ++jj) {
                int row = wn + jj * 16 + (lid & 15);
                int col = ks * 32 + (lid >> 4) * 16;
                ldsm_x4(bf[jj][0], bf[jj][1], bf[jj][2], bf[jj][3], Bsm + SWZ128(row * 128 + col));
            }
            #pragma unroll
            for (int i = 0; i < 2; ++i)
                #pragma unroll
                for (int j = 0; j < 8; ++j) {
                    unsigned bb[2] = { bf[j >> 1][j & 1], bf[j >> 1][2 + (j & 1)] };
                    mma_bf16(acc[i][j], a[i], bb);
                }
        }
        __syncthreads();
        if (kc + 2 < 16) load_stage(kc + 2, st);
        CP_COMMIT();
    }

    // epilogue: partial logit = sum_e tanh(acc + off[e]) * v[e] over this tile's 128 e's
    const float* off_s = (const float*)(smem + SM_OFF);
    const float* v_s   = (const float*)(smem + SM_V);
    float pr[2][2] = {{0.f, 0.f}, {0.f, 0.f}};   // [m16 tile][row half]
    #pragma unroll
    for (int i = 0; i < 2; ++i)
        #pragma unroll
        for (int j = 0; j < 8; ++j) {
            int el = wn + j * 8 + (lid & 3) * 2;
            float o0 = off_s[el], o1 = off_s[el + 1];
            float v0 = v_s[el],   v1 = v_s[el + 1];
            pr[i][0] = fmaf(tanh_fast(acc[i][j][0] + o0), v0, pr[i][0]);
            pr[i][0] = fmaf(tanh_fast(acc[i][j][1] + o1), v1, pr[i][0]);
            pr[i][1] = fmaf(tanh_fast(acc[i][j][2] + o0), v0, pr[i][1]);
            pr[i][1] = fmaf(tanh_fast(acc[i][j][3] + o1), v1, pr[i][1]);
        }
    #pragma unroll
    for (int o = 1; o <= 2; o <<= 1) {
        pr[0][0] += __shfl_xor_sync(0xffffffffu, pr[0][0], o);
        pr[0][1] += __shfl_xor_sync(0xffffffffu, pr[0][1], o);
        pr[1][0] += __shfl_xor_sync(0xffffffffu, pr[1][0], o);
        pr[1][1] += __shfl_xor_sync(0xffffffffu, pr[1][1], o);
    }
    float* part = (float*)(smem + SM_PART) + (wid >> 2) * 128;
    if ((lid & 3) == 0) {
        int g = lid >> 2;
        part[wm + g]          = pr[0][0];
        part[wm + g + 8]      = pr[0][1];
        part[wm + 16 + g]     = pr[1][0];
        part[wm + 16 + g + 8] = pr[1][1];
    }
    __syncthreads();
    if (tid < 128) {
        float sum = ((float*)(smem + SM_PART))[tid] + ((float*)(smem + SM_PART))[128 + tid];
        g_partial[((size_t)nt * BATCH + b) * SRCLEN + s0 + tid] = sum;
    }
}

// ---------------- kernel 4: reduce partials + softmax, writes align_vectors ----------------
__global__ void softmax_kernel(float* __restrict__ p_out) {
    __shared__ float red[256];
    const int b = blockIdx.x, t = threadIdx.x;
    float vals[8];
    float m = -1e30f;
    #pragma unroll
    for (int i = 0; i < 8; ++i) {
        size_t idx = (size_t)b * SRCLEN + t + i * 256;
        float s = 0.f;
        #pragma unroll
        for (int nt = 0; nt < 8; ++nt)
            s += g_partial[(size_t)nt * BATCH * SRCLEN + idx];
        vals[i] = s;
        m = fmaxf(m, s);
    }
    red[t] = m; __syncthreads();
    for (int o = 128; o > 0; o >>= 1) { if (t < o) red[t] = fmaxf(red[t], red[t + o]); __syncthreads(); }
    const float M = red[0]; __syncthreads();
    float s = 0.f;
    #pragma unroll
    for (int i = 0; i < 8; ++i) { vals[i] = __expf(vals[i] - M); s += vals[i]; }
    red[t] = s; __syncthreads();
    for (int o = 128; o > 0; o >>= 1) { if (t < o) red[t] += red[t + o]; __syncthreads(); }
    const float inv = 1.f / red[0];
    #pragma unroll
    for (int i = 0; i < 8; ++i)
        p_out[(size_t)b * SRCLEN + t + i * 256] = vals[i] * inv;
}

// ---------------- kernel 5: c[b,d] = sum_s p[b,s] * mem[b,s,d] (fp32) ----------------
__global__ void __launch_bounds__(256) context_kernel(const float* __restrict__ mem,
                                                      const float* __restrict__ p_all,
                                                      float* __restrict__ c_out) {
    __shared__ float p[SRCLEN];
    const int b = blockIdx.y, d0 = blockIdx.x * 256, t = threadIdx.x;
    for (int i = t; i < SRCLEN; i += 256) p[i] = p_all[(size_t)b * SRCLEN + i];
    __syncthreads();
    const float* mb = mem + (size_t)b * SRCLEN * DIM + d0 + t;
    float acc = 0.f;
    #pragma unroll 8
    for (int s = 0; s < SRCLEN; ++s)
        acc = fmaf(p[s], mb[(size_t)s * DIM], acc);
    c_out[(size_t)b * DIM + d0 + t] = acc;
}

// ---------------- launch ----------------
extern "C" void kernel_launch(void* const* d_in, const int* in_sizes, int n_in,
                              void* d_out, int out_size) {
    const float* source = (const float*)d_in[0];
    const float* mem    = (const float*)d_in[1];
    const float* cond   = (const float*)d_in[2];
    const float* Wq     = (const float*)d_in[3];
    const float* bq     = (const float*)d_in[4];
    const float* Wc     = (const float*)d_in[5];
    const float* Wcd    = (const float*)d_in[6];
    const float* v      = (const float*)d_in[7];

    float* out   = (float*)d_out;
    float* c_out = out;                    // [64, 1024]
    float* p_out = out + BATCH * DIM;      // [64, 1, 2048]

    void *pmem = nullptr, *pwc = nullptr;
    cudaGetSymbolAddress(&pmem, g_mem_bf16);
    cudaGetSymbolAddress(&pwc, g_wc_bf16);

    conv_f32_bf16<<<8192, 256>>>(mem, (__nv_bfloat16*)pmem, (size_t)BATCH * SRCLEN * DIM / 8);
    conv_f32_bf16<<<512, 256>>>(Wc, (__nv_bfloat16*)pwc, (size_t)DIM * DIM / 8);
    off_kernel<<<256, 256>>>(source, cond, Wq, bq, Wcd);

    static bool attr_set = false;
    if (!attr_set) {
        cudaFuncSetAttribute(gemm_align_kernel, cudaFuncAttributeMaxDynamicSharedMemorySize, SMEM_TOTAL);
        attr_set = true;
    }
    gemm_align_kernel<<<dim3(8, 16, 64), 256, SMEM_TOTAL>>>(v);

    softmax_kernel<<<64, 256>>>(p_out);
    context_kernel<<<dim3(4, 64), 256>>>(mem, p_out, c_out);
}

// round 14
// speedup vs baseline: 1.0065x; 1.0003x over previous
#include <cuda_runtime.h>
#include <cuda_bf16.h>

#define BATCH 64
#define SRCLEN 2048
#define DIM 1024

// ---------------- device scratch (no allocations allowed) ----------------
__device__ __nv_bfloat16 g_mem_bf16[(size_t)BATCH * SRCLEN * DIM];   // 256 MB
__device__ __nv_bfloat16 g_wc_bf16[DIM * DIM];                       // 2 MB
__device__ float         g_off[BATCH * DIM];                         // 256 KB
__device__ float         g_partial[8 * BATCH * SRCLEN];              // 4 MB

// ---------------- helpers (base ISA only: no 'a'-gated features) ----------------
__device__ __forceinline__ unsigned smem_u32(const void* p) {
    unsigned a;
    asm("{ .reg .u64 t; cvta.to.shared.u64 t, %1; cvt.u32.u64 %0, t; }" : "=r"(a) : "l"(p));
    return a;
}
__device__ __forceinline__ float tanh_fast(float x) {
    float y; asm("tanh.approx.f32 %0, %1;" : "=f"(y) : "f"(x)); return y;
}

#define SWZ128(o) ((o) ^ (((o) >> 3) & 0x70))

#define CP_ASYNC16(dst, src) \
    asm volatile("cp.async.cg.shared.global [%0], [%1], 16;" :: "r"(dst), "l"(src) : "memory")
#define CP_COMMIT() asm volatile("cp.async.commit_group;" ::: "memory")
#define CP_WAIT1()  asm volatile("cp.async.wait_group 1;" ::: "memory")

__device__ __forceinline__ void ldsm_x4(unsigned& r0, unsigned& r1, unsigned& r2, unsigned& r3,
                                        unsigned addr) {
    asm volatile("ldmatrix.sync.aligned.m8n8.x4.shared.b16 {%0,%1,%2,%3}, [%4];"
                 : "=r"(r0), "=r"(r1), "=r"(r2), "=r"(r3) : "r"(addr));
}

__device__ __forceinline__ void mma_bf16(float* d, const unsigned* a, const unsigned* b) {
    asm volatile(
        "mma.sync.aligned.m16n8k16.row.col.f32.bf16.bf16.f32 "
        "{%0,%1,%2,%3}, {%4,%5,%6,%7}, {%8,%9}, {%0,%1,%2,%3};"
        : "+f"(d[0]), "+f"(d[1]), "+f"(d[2]), "+f"(d[3])
        : "r"(a[0]), "r"(a[1]), "r"(a[2]), "r"(a[3]), "r"(b[0]), "r"(b[1]));
}

// ---------------- kernel 1: fp32 -> bf16 convert ----------------
__global__ void conv_f32_bf16(const float* __restrict__ src, __nv_bfloat16* __restrict__ dst, size_t n8) {
    size_t i = (size_t)blockIdx.x * blockDim.x + threadIdx.x;
    size_t stride = (size_t)gridDim.x * blockDim.x;
    for (; i < n8; i += stride) {
        float4 a = ((const float4*)src)[2 * i];
        float4 b = ((const float4*)src)[2 * i + 1];
        __nv_bfloat162 h0 = __floats2bfloat162_rn(a.x, a.y);
        __nv_bfloat162 h1 = __floats2bfloat162_rn(a.z, a.w);
        __nv_bfloat162 h2 = __floats2bfloat162_rn(b.x, b.y);
        __nv_bfloat162 h3 = __floats2bfloat162_rn(b.z, b.w);
        uint4 o;
        o.x = *reinterpret_cast<unsigned*>(&h0);
        o.y = *reinterpret_cast<unsigned*>(&h1);
        o.z = *reinterpret_cast<unsigned*>(&h2);
        o.w = *reinterpret_cast<unsigned*>(&h3);
        ((uint4*)dst)[i] = o;
    }
}

// ---------------- kernel 2: off[b,e] = bq[e] + src.Wq^T + cond.Wcond^T ----------------
__global__ void off_kernel(const float* __restrict__ src, const float* __restrict__ cond,
                           const float* __restrict__ Wq, const float* __restrict__ bq,
                           const float* __restrict__ Wcd) {
    __shared__ float Ws[2][4][DIM];  // 32 KB
    int e0 = blockIdx.x * 4;
    int t = threadIdx.x;
    for (int i = t; i < 2 * 4 * DIM; i += 256) {
        int m = i >> 12, r = (i >> 10) & 3, d = i & 1023;
        Ws[m][r][d] = (m ? Wcd : Wq)[(size_t)(e0 + r) * DIM + d];
    }
    __syncthreads();
    int w = t >> 5, l = t & 31;
    int el = w & 3;
    for (int b = (w >> 2); b < BATCH; b += 2) {
        float a1 = 0.f, a2 = 0.f;
        for (int d = l; d < DIM; d += 32) {
            a1 = fmaf(src[(size_t)b * DIM + d], Ws[0][el][d], a1);
            a2 = fmaf(cond[(size_t)b * DIM + d], Ws[1][el][d], a2);
        }
        for (int o = 16; o > 0; o >>= 1) {
            a1 += __shfl_down_sync(0xffffffffu, a1, o);
            a2 += __shfl_down_sync(0xffffffffu, a2, o);
        }
        if (l == 0) g_off[(size_t)b * DIM + e0 + el] = bq[e0 + el] + a1 + a2;
    }
}

// ---------------- kernel 3: mma.sync GEMM + fused tanh/v-dot epilogue ----------------
// CTA = 128 s-rows x 128 e-cols for one batch. grid = (8 ntile, 16 stile, 64 batch).
// Writes partial logits to g_partial[nt][b][s].
static constexpr int SM_A0 = 0;          // 16 KB (128 rows x 128B, SW128)
static constexpr int SM_A1 = 16384;
static constexpr int SM_B0 = 32768;      // 16 KB
static constexpr int SM_B1 = 49152;
static constexpr int SM_OFF = 65536;     // 512 B
static constexpr int SM_V   = 66048;     // 512 B
static constexpr int SM_PART = 66560;    // 2 x 128 x 4B = 1 KB
static constexpr int SMEM_TOTAL = 67584;

__global__ void __launch_bounds__(256, 2) gemm_align_kernel(const float* __restrict__ v) {
    extern __shared__ char smem[];
    const unsigned sb = smem_u32(smem);
    const int tid = threadIdx.x, wid = tid >> 5, lid = tid & 31;
    const int nt = blockIdx.x;           // e tile (0..7)
    const int s0 = blockIdx.y * 128;     // s tile
    const int b  = blockIdx.z;

    const __nv_bfloat16* Abase = g_mem_bf16 + ((size_t)b * SRCLEN + s0) * DIM;
    const __nv_bfloat16* Bbase = g_wc_bf16 + (size_t)nt * 128 * DIM;

    // stage offsets
    const int SMA[2] = {SM_A0, SM_A1};
    const int SMB[2] = {SM_B0, SM_B1};

    // load off/v slices for this e-tile
    if (tid < 128) {
        ((float*)(smem + SM_OFF))[tid] = g_off[(size_t)b * DIM + nt * 128 + tid];
        ((float*)(smem + SM_V))[tid] = v[nt * 128 + tid];
    }

    // async-load one 64-wide k-chunk (A and B tiles: 128 rows x 128B each)
    auto load_stage = [&](int kc, int st) {
        #pragma unroll
        for (int j = 0; j < 4; ++j) {
            int i = tid + j * 256;
            int r = i >> 3, c = i & 7;
            const void* srcA = Abase + (size_t)r * DIM + kc * 64 + c * 8;
            CP_ASYNC16(sb + SMA[st] + SWZ128(r * 128 + c * 16), srcA);
        }
        #pragma unroll
        for (int j = 0; j < 4; ++j) {
            int i = tid + j * 256;
            int r = i >> 3, c = i & 7;
            const void* srcB = Bbase + (size_t)r * DIM + kc * 64 + c * 8;
            CP_ASYNC16(sb + SMB[st] + SWZ128(r * 128 + c * 16), srcB);
        }
    };

    load_stage(0, 0); CP_COMMIT();
    load_stage(1, 1); CP_COMMIT();

    const int wm = (wid & 3) * 32;   // warp m offset (s rows)
    const int wn = (wid >> 2) * 64;  // warp n offset (e cols)

    float acc[2][8][4];
    #pragma unroll
    for (int i = 0; i < 2; ++i)
        #pragma unroll
        for (int j = 0; j < 8; ++j)
            #pragma unroll
            for (int q = 0; q < 4; ++q) acc[i][j][q] = 0.f;

    for (int kc = 0; kc < 16; ++kc) {
        CP_WAIT1();
        __syncthreads();
        const int st = kc & 1;
        const unsigned Asm = sb + SMA[st];
        const unsigned Bsm = sb + SMB[st];
        #pragma unroll
        for (int ks = 0; ks < 4; ++ks) {
            unsigned a[2][4];
            #pragma unroll
            for (int i = 0; i < 2; ++i) {
                int row = wm + i * 16 + (lid & 15);
                int col = ks * 32 + (lid >> 4) * 16;
                ldsm_x4(a[i][0], a[i][1], a[i][2], a[i][3], Asm + SWZ128(row * 128 + col));
            }
            unsigned bf[4][4];
            #pragma unroll
            for (int jj = 0; jj < 4; ++jj) {
                int row = wn + jj * 16 + (lid & 15);
                int col = ks * 32 + (lid >> 4) * 16;
                ldsm_x4(bf[jj][0], bf[jj][1], bf[jj][2], bf[jj][3], Bsm + SWZ128(row * 128 + col));
            }
            #pragma unroll
            for (int i = 0; i < 2; ++i)
                #pragma unroll
                for (int j = 0; j < 8; ++j) {
                    unsigned bb[2] = { bf[j >> 1][j & 1], bf[j >> 1][2 + (j & 1)] };
                    mma_bf16(acc[i][j], a[i], bb);
                }
        }
        __syncthreads();
        if (kc + 2 < 16) load_stage(kc + 2, st);
        CP_COMMIT();
    }

    // epilogue: partial logit = sum_e tanh(acc + off[e]) * v[e] over this tile's 128 e's
    const float* off_s = (const float*)(smem + SM_OFF);
    const float* v_s   = (const float*)(smem + SM_V);
    float pr[2][2] = {{0.f, 0.f}, {0.f, 0.f}};   // [m16 tile][row half]
    #pragma unroll
    for (int i = 0; i < 2; ++i)
        #pragma unroll
        for (int j = 0; j < 8; ++j) {
            int el = wn + j * 8 + (lid & 3) * 2;
            float o0 = off_s[el], o1 = off_s[el + 1];
            float v0 = v_s[el],   v1 = v_s[el + 1];
            pr[i][0] = fmaf(tanh_fast(acc[i][j][0] + o0), v0, pr[i][0]);
            pr[i][0] = fmaf(tanh_fast(acc[i][j][1] + o1), v1, pr[i][0]);
            pr[i][1] = fmaf(tanh_fast(acc[i][j][2] + o0), v0, pr[i][1]);
            pr[i][1] = fmaf(tanh_fast(acc[i][j][3] + o1), v1, pr[i][1]);
        }
    #pragma unroll
    for (int o = 1; o <= 2; o <<= 1) {
        pr[0][0] += __shfl_xor_sync(0xffffffffu, pr[0][0], o);
        pr[0][1] += __shfl_xor_sync(0xffffffffu, pr[0][1], o);
        pr[1][0] += __shfl_xor_sync(0xffffffffu, pr[1][0], o);
        pr[1][1] += __shfl_xor_sync(0xffffffffu, pr[1][1], o);
    }
    float* part = (float*)(smem + SM_PART) + (wid >> 2) * 128;
    if ((lid & 3) == 0) {
        int g = lid >> 2;
        part[wm + g]          = pr[0][0];
        part[wm + g + 8]      = pr[0][1];
        part[wm + 16 + g]     = pr[1][0];
        part[wm + 16 + g + 8] = pr[1][1];
    }
    __syncthreads();
    if (tid < 128) {
        float sum = ((float*)(smem + SM_PART))[tid] + ((float*)(smem + SM_PART))[128 + tid];
        g_partial[((size_t)nt * BATCH + b) * SRCLEN + s0 + tid] = sum;
    }
}

// ---------------- kernel 4: reduce partials + softmax, writes align_vectors ----------------
__global__ void softmax_kernel(float* __restrict__ p_out) {
    __shared__ float red[256];
    const int b = blockIdx.x, t = threadIdx.x;
    float vals[8];
    float m = -1e30f;
    #pragma unroll
    for (int i = 0; i < 8; ++i) {
        size_t idx = (size_t)b * SRCLEN + t + i * 256;
        float s = 0.f;
        #pragma unroll
        for (int nt = 0; nt < 8; ++nt)
            s += g_partial[(size_t)nt * BATCH * SRCLEN + idx];
        vals[i] = s;
        m = fmaxf(m, s);
    }
    red[t] = m; __syncthreads();
    for (int o = 128; o > 0; o >>= 1) { if (t < o) red[t] = fmaxf(red[t], red[t + o]); __syncthreads(); }
    const float M = red[0]; __syncthreads();
    float s = 0.f;
    #pragma unroll
    for (int i = 0; i < 8; ++i) { vals[i] = __expf(vals[i] - M); s += vals[i]; }
    red[t] = s; __syncthreads();
    for (int o = 128; o > 0; o >>= 1) { if (t < o) red[t] += red[t + o]; __syncthreads(); }
    const float inv = 1.f / red[0];
    #pragma unroll
    for (int i = 0; i < 8; ++i)
        p_out[(size_t)b * SRCLEN + t + i * 256] = vals[i] * inv;
}

// ---------------- kernel 5: c[b,d] = sum_s p[b,s] * mem[b,s,d] (fp32) ----------------
__global__ void __launch_bounds__(256) context_kernel(const float* __restrict__ mem,
                                                      const float* __restrict__ p_all,
                                                      float* __restrict__ c_out) {
    __shared__ float p[SRCLEN];
    const int b = blockIdx.y, d0 = blockIdx.x * 256, t = threadIdx.x;
    for (int i = t; i < SRCLEN; i += 256) p[i] = p_all[(size_t)b * SRCLEN + i];
    __syncthreads();
    const float* mb = mem + (size_t)b * SRCLEN * DIM + d0 + t;
    float acc = 0.f;
    #pragma unroll 8
    for (int s = 0; s < SRCLEN; ++s)
        acc = fmaf(p[s], mb[(size_t)s * DIM], acc);
    c_out[(size_t)b * DIM + d0 + t] = acc;
}

// ---------------- launch ----------------
extern "C" void kernel_launch(void* const* d_in, const int* in_sizes, int n_in,
                              void* d_out, int out_size) {
    const float* source = (const float*)d_in[0];
    const float* mem    = (const float*)d_in[1];
    const float* cond   = (const float*)d_in[2];
    const float* Wq     = (const float*)d_in[3];
    const float* bq     = (const float*)d_in[4];
    const float* Wc     = (const float*)d_in[5];
    const float* Wcd    = (const float*)d_in[6];
    const float* v      = (const float*)d_in[7];

    float* out   = (float*)d_out;
    float* c_out = out;                    // [64, 1024]
    float* p_out = out + BATCH * DIM;      // [64, 1, 2048]

    void *pmem = nullptr, *pwc = nullptr;
    cudaGetSymbolAddress(&pmem, g_mem_bf16);
    cudaGetSymbolAddress(&pwc, g_wc_bf16);

    conv_f32_bf16<<<8192, 256>>>(mem, (__nv_bfloat16*)pmem, (size_t)BATCH * SRCLEN * DIM / 8);
    conv_f32_bf16<<<512, 256>>>(Wc, (__nv_bfloat16*)pwc, (size_t)DIM * DIM / 8);
    off_kernel<<<256, 256>>>(source, cond, Wq, bq, Wcd);

    static bool attr_set = false;
    if (!attr_set) {
        cudaFuncSetAttribute(gemm_align_kernel, cudaFuncAttributeMaxDynamicSharedMemorySize, SMEM_TOTAL);
        attr_set = true;
    }
    gemm_align_kernel<<<dim3(8, 16, 64), 256, SMEM_TOTAL>>>(v);

    softmax_kernel<<<64, 256>>>(p_out);
    context_kernel<<<dim3(4, 64), 256>>>(mem, p_out, c_out);
}

// round 15
// speedup vs baseline: 1.0329x; 1.0262x over previous
#include <cuda_runtime.h>
#include <cuda_bf16.h>

#define BATCH 64
#define SRCLEN 2048
#define DIM 1024

// ---------------- device scratch (no allocations allowed) ----------------
__device__ __nv_bfloat16 g_mem_bf16[(size_t)BATCH * SRCLEN * DIM];   // 256 MB
__device__ __nv_bfloat16 g_wc_bf16[DIM * DIM];                       // 2 MB
__device__ float         g_off[BATCH * DIM];                         // 256 KB
__device__ float         g_partial[8 * BATCH * SRCLEN];              // 4 MB

// ---------------- helpers (base ISA only: no 'a'-gated features) ----------------
__device__ __forceinline__ unsigned smem_u32(const void* p) {
    unsigned a;
    asm("{ .reg .u64 t; cvta.to.shared.u64 t, %1; cvt.u32.u64 %0, t; }" : "=r"(a) : "l"(p));
    return a;
}
__device__ __forceinline__ float tanh_fast(float x) {
    float y; asm("tanh.approx.f32 %0, %1;" : "=f"(y) : "f"(x)); return y;
}

#define SWZ128(o) ((o) ^ (((o) >> 3) & 0x70))

#define CP_ASYNC16(dst, src) \
    asm volatile("cp.async.cg.shared.global [%0], [%1], 16;" :: "r"(dst), "l"(src) : "memory")
#define CP_COMMIT() asm volatile("cp.async.commit_group;" ::: "memory")
#define CP_WAIT1()  asm volatile("cp.async.wait_group 1;" ::: "memory")

__device__ __forceinline__ void ldsm_x4(unsigned& r0, unsigned& r1, unsigned& r2, unsigned& r3,
                                        unsigned addr) {
    asm volatile("ldmatrix.sync.aligned.m8n8.x4.shared.b16 {%0,%1,%2,%3}, [%4];"
                 : "=r"(r0), "=r"(r1), "=r"(r2), "=r"(r3) : "r"(addr));
}

__device__ __forceinline__ void mma_bf16(float* d, const unsigned* a, unsigned b0, unsigned b1) {
    asm volatile(
        "mma.sync.aligned.m16n8k16.row.col.f32.bf16.bf16.f32 "
        "{%0,%1,%2,%3}, {%4,%5,%6,%7}, {%8,%9}, {%0,%1,%2,%3};"
        : "+f"(d[0]), "+f"(d[1]), "+f"(d[2]), "+f"(d[3])
        : "r"(a[0]), "r"(a[1]), "r"(a[2]), "r"(a[3]), "r"(b0), "r"(b1));
}

// ---------------- kernel 1: fp32 -> bf16 convert ----------------
__global__ void conv_f32_bf16(const float* __restrict__ src, __nv_bfloat16* __restrict__ dst, size_t n8) {
    size_t i = (size_t)blockIdx.x * blockDim.x + threadIdx.x;
    size_t stride = (size_t)gridDim.x * blockDim.x;
    for (; i < n8; i += stride) {
        float4 a = ((const float4*)src)[2 * i];
        float4 b = ((const float4*)src)[2 * i + 1];
        __nv_bfloat162 h0 = __floats2bfloat162_rn(a.x, a.y);
        __nv_bfloat162 h1 = __floats2bfloat162_rn(a.z, a.w);
        __nv_bfloat162 h2 = __floats2bfloat162_rn(b.x, b.y);
        __nv_bfloat162 h3 = __floats2bfloat162_rn(b.z, b.w);
        uint4 o;
        o.x = *reinterpret_cast<unsigned*>(&h0);
        o.y = *reinterpret_cast<unsigned*>(&h1);
        o.z = *reinterpret_cast<unsigned*>(&h2);
        o.w = *reinterpret_cast<unsigned*>(&h3);
        ((uint4*)dst)[i] = o;
    }
}

// ---------------- kernel 2: off[b,e] = bq[e] + src.Wq^T + cond.Wcond^T ----------------
__global__ void off_kernel(const float* __restrict__ src, const float* __restrict__ cond,
                           const float* __restrict__ Wq, const float* __restrict__ bq,
                           const float* __restrict__ Wcd) {
    __shared__ float Ws[2][4][DIM];  // 32 KB
    int e0 = blockIdx.x * 4;
    int t = threadIdx.x;
    for (int i = t; i < 2 * 4 * DIM; i += 256) {
        int m = i >> 12, r = (i >> 10) & 3, d = i & 1023;
        Ws[m][r][d] = (m ? Wcd : Wq)[(size_t)(e0 + r) * DIM + d];
    }
    __syncthreads();
    int w = t >> 5, l = t & 31;
    int el = w & 3;
    for (int b = (w >> 2); b < BATCH; b += 2) {
        float a1 = 0.f, a2 = 0.f;
        for (int d = l; d < DIM; d += 32) {
            a1 = fmaf(src[(size_t)b * DIM + d], Ws[0][el][d], a1);
            a2 = fmaf(cond[(size_t)b * DIM + d], Ws[1][el][d], a2);
        }
        for (int o = 16; o > 0; o >>= 1) {
            a1 += __shfl_down_sync(0xffffffffu, a1, o);
            a2 += __shfl_down_sync(0xffffffffu, a2, o);
        }
        if (l == 0) g_off[(size_t)b * DIM + e0 + el] = bq[e0 + el] + a1 + a2;
    }
}

// ---------------- kernel 3: mma.sync GEMM + fused tanh/v-dot epilogue ----------------
// CTA = 128 s-rows x 128 e-cols for one batch. grid = (8 ntile, 16 stile, 64 batch).
// 3-stage cp.async pipeline; all ldmatrix/cp.async swizzle math hoisted.
static constexpr int STAGE_BYTES = 32768;            // A 16KB + B 16KB
static constexpr int SM_OFF  = 3 * STAGE_BYTES;      // 98304, 512 B
static constexpr int SM_V    = SM_OFF + 512;
static constexpr int SM_PART = SM_V + 512;           // 1 KB
static constexpr int SMEM_TOTAL = SM_PART + 1024;    // 100352 B

__global__ void __launch_bounds__(256, 2) gemm_align_kernel(const float* __restrict__ v) {
    extern __shared__ char smem[];
    const unsigned sb = smem_u32(smem);
    const int tid = threadIdx.x, wid = tid >> 5, lid = tid & 31;
    const int nt = blockIdx.x;           // e tile (0..7)
    const int s0 = blockIdx.y * 128;     // s tile
    const int b  = blockIdx.z;

    // ---- hoisted cp.async addressing: r=(tid>>3)+j*32, c=tid&7 ----
    // SWZ128(r*128+c*16) = r*128 + (c*16 ^ ((r&7)*16)); (r&7) is j-invariant.
    const int ldr = tid >> 3, ldc = tid & 7;
    const unsigned sSwz = (unsigned)(ldr * 128 + ((ldc * 16) ^ ((ldr & 7) * 16)));
    const __nv_bfloat16* gA = g_mem_bf16 + ((size_t)b * SRCLEN + s0 + ldr) * DIM + ldc * 8;
    const __nv_bfloat16* gB = g_wc_bf16 + ((size_t)nt * 128 + ldr) * DIM + ldc * 8;

    const unsigned stb[3] = { sb, sb + STAGE_BYTES, sb + 2 * STAGE_BYTES };

    // load off/v slices for this e-tile
    if (tid < 128) {
        ((float*)(smem + SM_OFF))[tid] = g_off[(size_t)b * DIM + nt * 128 + tid];
        ((float*)(smem + SM_V))[tid] = v[nt * 128 + tid];
    }

    auto load_stage = [&](int kc, unsigned base) {
        const __nv_bfloat16* a = gA + kc * 64;
        const __nv_bfloat16* bb = gB + kc * 64;
        #pragma unroll
        for (int j = 0; j < 4; ++j)
            CP_ASYNC16(base + sSwz + j * 4096, a + (size_t)j * 32 * DIM);
        #pragma unroll
        for (int j = 0; j < 4; ++j)
            CP_ASYNC16(base + 16384 + sSwz + j * 4096, bb + (size_t)j * 32 * DIM);
    };

    load_stage(0, stb[0]); CP_COMMIT();
    load_stage(1, stb[1]); CP_COMMIT();

    const int wm = (wid & 3) * 32;   // warp m offset (s rows)
    const int wn = (wid >> 2) * 64;  // warp n offset (e cols)

    // ---- hoisted ldmatrix addressing ----
    // SWZ128(row*128+col) = row*128 + (col ^ ((lid&7)*16)) since row&7 == lid&7 here.
    const unsigned xorv = (unsigned)((lid & 7) * 16);
    const unsigned colb = (unsigned)((lid >> 4) * 16);
    unsigned colk[4];
    #pragma unroll
    for (int ks = 0; ks < 4; ++ks) colk[ks] = (unsigned)(ks * 32 + colb) ^ xorv;
    const unsigned rA0 = (unsigned)((wm + (lid & 15)) * 128);
    const unsigned rA1 = rA0 + 16 * 128;
    unsigned rB[4];
    #pragma unroll
    for (int jj = 0; jj < 4; ++jj) rB[jj] = (unsigned)((wn + jj * 16 + (lid & 15)) * 128);

    float acc[2][8][4];
    #pragma unroll
    for (int i = 0; i < 2; ++i)
        #pragma unroll
        for (int j = 0; j < 8; ++j)
            #pragma unroll
            for (int q = 0; q < 4; ++q) acc[i][j][q] = 0.f;

    int stC = 0, stL = 2;  // consume stage, load stage
    #pragma unroll 1
    for (int kc = 0; kc < 16; ++kc) {
        CP_WAIT1();
        __syncthreads();
        if (kc + 2 < 16) load_stage(kc + 2, stb[stL]);
        CP_COMMIT();  // empty commits in tail keep the wait_group invariant
        const unsigned As = stb[stC];
        const unsigned Bs = As + 16384;
        #pragma unroll
        for (int ks = 0; ks < 4; ++ks) {
            unsigned a0[4], a1[4];
            ldsm_x4(a0[0], a0[1], a0[2], a0[3], As + rA0 + colk[ks]);
            ldsm_x4(a1[0], a1[1], a1[2], a1[3], As + rA1 + colk[ks]);
            #pragma unroll
            for (int jj = 0; jj < 4; ++jj) {
                unsigned b0, b1, b2, b3;
                ldsm_x4(b0, b1, b2, b3, Bs + rB[jj] + colk[ks]);
                mma_bf16(acc[0][2 * jj],     a0, b0, b2);
                mma_bf16(acc[0][2 * jj + 1], a0, b1, b3);
                mma_bf16(acc[1][2 * jj],     a1, b0, b2);
                mma_bf16(acc[1][2 * jj + 1], a1, b1, b3);
            }
        }
        if (++stC == 3) stC = 0;
        if (++stL == 3) stL = 0;
    }

    // epilogue: partial logit = sum_e tanh(acc + off[e]) * v[e] over this tile's 128 e's
    const float* off_s = (const float*)(smem + SM_OFF);
    const float* v_s   = (const float*)(smem + SM_V);
    float pr[2][2] = {{0.f, 0.f}, {0.f, 0.f}};   // [m16 tile][row half]
    #pragma unroll
    for (int i = 0; i < 2; ++i)
        #pragma unroll
        for (int j = 0; j < 8; ++j) {
            int el = wn + j * 8 + (lid & 3) * 2;
            float o0 = off_s[el], o1 = off_s[el + 1];
            float v0 = v_s[el],   v1 = v_s[el + 1];
            pr[i][0] = fmaf(tanh_fast(acc[i][j][0] + o0), v0, pr[i][0]);
            pr[i][0] = fmaf(tanh_fast(acc[i][j][1] + o1), v1, pr[i][0]);
            pr[i][1] = fmaf(tanh_fast(acc[i][j][2] + o0), v0, pr[i][1]);
            pr[i][1] = fmaf(tanh_fast(acc[i][j][3] + o1), v1, pr[i][1]);
        }
    #pragma unroll
    for (int o = 1; o <= 2; o <<= 1) {
        pr[0][0] += __shfl_xor_sync(0xffffffffu, pr[0][0], o);
        pr[0][1] += __shfl_xor_sync(0xffffffffu, pr[0][1], o);
        pr[1][0] += __shfl_xor_sync(0xffffffffu, pr[1][0], o);
        pr[1][1] += __shfl_xor_sync(0xffffffffu, pr[1][1], o);
    }
    float* part = (float*)(smem + SM_PART) + (wid >> 2) * 128;
    if ((lid & 3) == 0) {
        int g = lid >> 2;
        part[wm + g]          = pr[0][0];
        part[wm + g + 8]      = pr[0][1];
        part[wm + 16 + g]     = pr[1][0];
        part[wm + 16 + g + 8] = pr[1][1];
    }
    __syncthreads();
    if (tid < 128) {
        float sum = ((float*)(smem + SM_PART))[tid] + ((float*)(smem + SM_PART))[128 + tid];
        g_partial[((size_t)nt * BATCH + b) * SRCLEN + s0 + tid] = sum;
    }
}

// ---------------- kernel 4: reduce partials + softmax, writes align_vectors ----------------
__global__ void softmax_kernel(float* __restrict__ p_out) {
    __shared__ float red[256];
    const int b = blockIdx.x, t = threadIdx.x;
    float vals[8];
    float m = -1e30f;
    #pragma unroll
    for (int i = 0; i < 8; ++i) {
        size_t idx = (size_t)b * SRCLEN + t + i * 256;
        float s = 0.f;
        #pragma unroll
        for (int nt = 0; nt < 8; ++nt)
            s += g_partial[(size_t)nt * BATCH * SRCLEN + idx];
        vals[i] = s;
        m = fmaxf(m, s);
    }
    red[t] = m; __syncthreads();
    for (int o = 128; o > 0; o >>= 1) { if (t < o) red[t] = fmaxf(red[t], red[t + o]); __syncthreads(); }
    const float M = red[0]; __syncthreads();
    float s = 0.f;
    #pragma unroll
    for (int i = 0; i < 8; ++i) { vals[i] = __expf(vals[i] - M); s += vals[i]; }
    red[t] = s; __syncthreads();
    for (int o = 128; o > 0; o >>= 1) { if (t < o) red[t] += red[t + o]; __syncthreads(); }
    const float inv = 1.f / red[0];
    #pragma unroll
    for (int i = 0; i < 8; ++i)
        p_out[(size_t)b * SRCLEN + t + i * 256] = vals[i] * inv;
}

// ---------------- kernel 5: c[b,d] = sum_s p[b,s] * mem[b,s,d] (fp32) ----------------
__global__ void __launch_bounds__(256) context_kernel(const float* __restrict__ mem,
                                                      const float* __restrict__ p_all,
                                                      float* __restrict__ c_out) {
    __shared__ float p[SRCLEN];
    const int b = blockIdx.y, d0 = blockIdx.x * 256, t = threadIdx.x;
    for (int i = t; i < SRCLEN; i += 256) p[i] = p_all[(size_t)b * SRCLEN + i];
    __syncthreads();
    const float* mb = mem + (size_t)b * SRCLEN * DIM + d0 + t;
    float acc = 0.f;
    #pragma unroll 8
    for (int s = 0; s < SRCLEN; ++s)
        acc = fmaf(p[s], mb[(size_t)s * DIM], acc);
    c_out[(size_t)b * DIM + d0 + t] = acc;
}

// ---------------- launch ----------------
extern "C" void kernel_launch(void* const* d_in, const int* in_sizes, int n_in,
                              void* d_out, int out_size) {
    const float* source = (const float*)d_in[0];
    const float* mem    = (const float*)d_in[1];
    const float* cond   = (const float*)d_in[2];
    const float* Wq     = (const float*)d_in[3];
    const float* bq     = (const float*)d_in[4];
    const float* Wc     = (const float*)d_in[5];
    const float* Wcd    = (const float*)d_in[6];
    const float* v      = (const float*)d_in[7];

    float* out   = (float*)d_out;
    float* c_out = out;                    // [64, 1024]
    float* p_out = out + BATCH * DIM;      // [64, 1, 2048]

    void *pmem = nullptr, *pwc = nullptr;
    cudaGetSymbolAddress(&pmem, g_mem_bf16);
    cudaGetSymbolAddress(&pwc, g_wc_bf16);

    conv_f32_bf16<<<8192, 256>>>(mem, (__nv_bfloat16*)pmem, (size_t)BATCH * SRCLEN * DIM / 8);
    conv_f32_bf16<<<512, 256>>>(Wc, (__nv_bfloat16*)pwc, (size_t)DIM * DIM / 8);
    off_kernel<<<256, 256>>>(source, cond, Wq, bq, Wcd);

    static bool attr_set = false;
    if (!attr_set) {
        cudaFuncSetAttribute(gemm_align_kernel, cudaFuncAttributeMaxDynamicSharedMemorySize, SMEM_TOTAL);
        attr_set = true;
    }
    gemm_align_kernel<<<dim3(8, 16, 64), 256, SMEM_TOTAL>>>(v);

    softmax_kernel<<<64, 256>>>(p_out);
    context_kernel<<<dim3(4, 64), 256>>>(mem, p_out, c_out);
}